// round 14
// baseline (speedup 1.0000x reference)
#include <cuda_runtime.h>

// Problem constants: NP=44 tiny MLPs, B=400000 batch.
#define NP_   44
#define B_    400000
#define B4_   (B_ / 4)            // 100000 float4 per l
#define N4_   (NP_ * B4_)         // 4,400,000 float4 total
#define TPB   256
#define NBLK  1216                // ~8 blocks/SM on 152 SMs -> ~full occupancy
#define VPT   4

// Weight smem layout: [0:176) w1, [176:1584) w2, [1584:2992) w3, [2992:3168) w4
#define W1OFF 0
#define W2OFF 176
#define W3OFF 1584
#define W4OFF 2992
#define WTOT  3168

// Fully-occupant flat streaming kernel.
// Math: input is a scalar per element, so the whole 1->4->8->4->1 ReLU MLP
// collapses to out = (x>0 ? s_pos[l] : s_neg[l]) * x. Each block builds the
// 44-entry (s_pos, s_neg) LUT in smem (cooperative weight load + 88 parallel
// scale computations), then grid-strides the flat float4 array with 4
// front-batched loads per iteration and evict-first stores.
__global__ __launch_bounds__(TPB, 8) void fused_mlp_stream(
    const float4* __restrict__ X, float4* __restrict__ O,
    const float* __restrict__ w1,   // (NP,4,1)
    const float* __restrict__ w2,   // (NP,8,4)
    const float* __restrict__ w3,   // (NP,4,8)
    const float* __restrict__ w4) { // (NP,1,4)

    __shared__ float  sw[WTOT];
    __shared__ float2 s_lut[NP_];   // .x = scale for x>0, .y = scale for x<0

    const int t = threadIdx.x;

    // Cooperative weight fetch: 3168 floats, 256 threads, ~12 loads each.
    #pragma unroll
    for (int i = t; i < WTOT; i += TPB) {
        float v;
        if      (i < W2OFF) v = w1[i];
        else if (i < W3OFF) v = w2[i - W2OFF];
        else if (i < W4OFF) v = w3[i - W3OFF];
        else                v = w4[i - W4OFF];
        sw[i] = v;
    }
    __syncthreads();

    // 88 threads each compute one (l, sign) collapsed scalar.
    if (t < 2 * NP_) {
        const int  l   = t >> 1;
        const bool pos = ((t & 1) == 0);
        const float* W1 = sw + W1OFF + l * 4;
        const float* W2 = sw + W2OFF + l * 32;
        const float* W3 = sw + W3OFF + l * 32;
        const float* W4 = sw + W4OFF + l * 4;
        float a[4];
        #pragma unroll
        for (int i = 0; i < 4; ++i) {
            float w = W1[i];
            a[i] = (pos ? (w > 0.0f) : (w < 0.0f)) ? w : 0.0f;
        }
        float b[8];
        #pragma unroll
        for (int j = 0; j < 8; ++j) {
            float s = 0.0f;
            #pragma unroll
            for (int i = 0; i < 4; ++i) s += W2[j * 4 + i] * a[i];
            b[j] = (pos ? (s > 0.0f) : (s < 0.0f)) ? s : 0.0f;
        }
        float c[4];
        #pragma unroll
        for (int i = 0; i < 4; ++i) {
            float s = 0.0f;
            #pragma unroll
            for (int j = 0; j < 8; ++j) s += W3[i * 8 + j] * b[j];
            c[i] = (pos ? (s > 0.0f) : (s < 0.0f)) ? s : 0.0f;
        }
        float out = 0.0f;
        #pragma unroll
        for (int i = 0; i < 4; ++i) out += W4[i] * c[i];
        if (pos) s_lut[l].x = out; else s_lut[l].y = out;
    }
    __syncthreads();

    const unsigned stride = NBLK * TPB;            // 311,296
    unsigned i = blockIdx.x * TPB + t;

    // Batched main loop: 4 independent float4 loads in flight per iteration.
    while (i + 3u * stride < N4_) {
        float4 v[VPT];
        #pragma unroll
        for (int k = 0; k < VPT; ++k)
            v[k] = X[i + (unsigned)k * stride];
        #pragma unroll
        for (int k = 0; k < VPT; ++k) {
            const unsigned idx = i + (unsigned)k * stride;
            const float2 s = s_lut[idx / (unsigned)B4_];   // broadcast LDS
            float4 x = v[k], o;
            o.x = (x.x > 0.0f ? s.x : s.y) * x.x;
            o.y = (x.y > 0.0f ? s.x : s.y) * x.y;
            o.z = (x.z > 0.0f ? s.x : s.y) * x.z;
            o.w = (x.w > 0.0f ? s.x : s.y) * x.w;
            __stcs(&O[idx], o);
        }
        i += VPT * stride;
    }
    // Remainder (at most 3 strided singles per thread).
    while (i < N4_) {
        const float2 s = s_lut[i / (unsigned)B4_];
        float4 x = X[i], o;
        o.x = (x.x > 0.0f ? s.x : s.y) * x.x;
        o.y = (x.y > 0.0f ? s.x : s.y) * x.y;
        o.z = (x.z > 0.0f ? s.x : s.y) * x.z;
        o.w = (x.w > 0.0f ? s.x : s.y) * x.w;
        __stcs(&O[i], o);
        i += stride;
    }
}

extern "C" void kernel_launch(void* const* d_in, const int* in_sizes, int n_in,
                              void* d_out, int out_size) {
    const float* X  = (const float*)d_in[0];
    const float* w1 = (const float*)d_in[1];
    const float* w2 = (const float*)d_in[2];
    const float* w3 = (const float*)d_in[3];
    const float* w4 = (const float*)d_in[4];
    float* out = (float*)d_out;

    fused_mlp_stream<<<NBLK, TPB>>>((const float4*)X, (float4*)out,
                                    w1, w2, w3, w4);
}

// round 15
// speedup vs baseline: 1.0908x; 1.0908x over previous
#include <cuda_runtime.h>

// Problem constants: NP=44 tiny MLPs, B=400000 batch.
#define NP_  44
#define B_   400000
#define B4_  (B_ / 4)          // 100000 float4 per l  (= 32 * 3125)
#define TPB  160               // 5 warps
#define VPT  5                 // float4s in flight per iteration
#define ITER 5                 // iterations per block
#define STEP (TPB * VPT)       // 800 float4 per iteration
#define CHUNK (STEP * ITER)    // 4000 float4 per block; 100000/4000 = 25 exact

// Fused kernel, R10 structure with the L2 residency policy FLIPPED:
//   - X loaded with __ldcs (evict-first streaming read -> served from DRAM,
//     does not occupy L2)
//   - O stored with plain write-allocate stores -> stays dirty in L2 and is
//     overwritten in place on the next graph replay, so steady-state DRAM
//     write traffic collapses; DRAM carries only the read stream.
// Math: input is scalar per element, so the 1->4->8->4->1 ReLU MLP collapses
// to out = (x>0 ? s_pos[l] : s_neg[l]) * x.
__global__ __launch_bounds__(TPB, 10) void fused_mlp_stream(
    const float4* __restrict__ X, float4* __restrict__ O,
    const float* __restrict__ w1,   // (NP,4,1)
    const float* __restrict__ w2,   // (NP,8,4)
    const float* __restrict__ w3,   // (NP,4,8)
    const float* __restrict__ w4) { // (NP,1,4)

    __shared__ float sw[72];        // [0:4) w1, [4:36) w2, [36:68) w3, [68:72) w4
    __shared__ float s_scale[2];

    const int l = blockIdx.y;
    const int t = threadIdx.x;

    // Parallel weight fetch (lanes 0..71, one load each).
    if (t < 72) {
        float v;
        if      (t < 4)  v = w1[l * 4  + t];
        else if (t < 36) v = w2[l * 32 + (t - 4)];
        else if (t < 68) v = w3[l * 32 + (t - 36)];
        else             v = w4[l * 4  + (t - 68)];
        sw[t] = v;
    }
    __syncthreads();

    // Two threads compute the two collapsed scalars (t=0: x>0, t=1: x<0).
    if (t < 2) {
        const bool pos = (t == 0);
        const float* W1 = sw;
        const float* W2 = sw + 4;
        const float* W3 = sw + 36;
        const float* W4 = sw + 68;
        float a[4];
        #pragma unroll
        for (int i = 0; i < 4; ++i) {
            float w = W1[i];
            a[i] = (pos ? (w > 0.0f) : (w < 0.0f)) ? w : 0.0f;
        }
        float b[8];
        #pragma unroll
        for (int j = 0; j < 8; ++j) {
            float s = 0.0f;
            #pragma unroll
            for (int i = 0; i < 4; ++i) s += W2[j * 4 + i] * a[i];
            b[j] = (pos ? (s > 0.0f) : (s < 0.0f)) ? s : 0.0f;
        }
        float c[4];
        #pragma unroll
        for (int i = 0; i < 4; ++i) {
            float s = 0.0f;
            #pragma unroll
            for (int j = 0; j < 8; ++j) s += W3[i * 8 + j] * b[j];
            c[i] = (pos ? (s > 0.0f) : (s < 0.0f)) ? s : 0.0f;
        }
        float out = 0.0f;
        #pragma unroll
        for (int i = 0; i < 4; ++i) out += W4[i] * c[i];
        s_scale[t] = out;
    }
    __syncthreads();

    const float sp = s_scale[0];
    const float sn = s_scale[1];

    // Base of this block's exact 4000-float4 region within its l.
    const float4* __restrict__ xi = X + (long)l * B4_ + blockIdx.x * CHUNK + t;
    float4*       __restrict__ oi = O + (long)l * B4_ + blockIdx.x * CHUNK + t;

    #pragma unroll
    for (int it = 0; it < ITER; ++it) {
        float4 x[VPT];
        #pragma unroll
        for (int k = 0; k < VPT; ++k)
            x[k] = __ldcs(&xi[k * TPB]);          // streaming read: keep X out of L2
        #pragma unroll
        for (int k = 0; k < VPT; ++k) {
            float4 v = x[k];
            float4 o;
            o.x = (v.x > 0.0f ? sp : sn) * v.x;
            o.y = (v.y > 0.0f ? sp : sn) * v.y;
            o.z = (v.z > 0.0f ? sp : sn) * v.z;
            o.w = (v.w > 0.0f ? sp : sn) * v.w;
            oi[k * TPB] = o;                       // write-allocate: keep O resident in L2
        }
        xi += STEP;
        oi += STEP;
    }
}

extern "C" void kernel_launch(void* const* d_in, const int* in_sizes, int n_in,
                              void* d_out, int out_size) {
    const float* X  = (const float*)d_in[0];
    const float* w1 = (const float*)d_in[1];
    const float* w2 = (const float*)d_in[2];
    const float* w3 = (const float*)d_in[3];
    const float* w4 = (const float*)d_in[4];
    float* out = (float*)d_out;

    dim3 grid(B4_ / CHUNK, NP_);   // (25, 44) = 1100 blocks, exact
    fused_mlp_stream<<<grid, TPB>>>((const float4*)X, (float4*)out,
                                    w1, w2, w3, w4);
}

// round 16
// speedup vs baseline: 1.1014x; 1.0097x over previous
#include <cuda_runtime.h>

// Problem constants: NP=44 tiny MLPs, B=400000 batch.
#define NP_  44
#define B_   400000
#define B4_  (B_ / 4)          // 100000 float4 per l  (= 32 * 3125)
#define TPB  160               // 5 warps
#define VPT  5                 // float4s in flight per iteration
#define ITER 5                 // iterations per block
#define STEP (TPB * VPT)       // 800 float4 per iteration
#define CHUNK (STEP * ITER)    // 4000 float4 per block; 100000/4000 = 25 exact

// Converged design. The problem is a pure stream at the LTS cap:
// 140.8 MB compulsory traffic / ~6300 B/cyc full-chip LTS ceiling ~= 20 us.
// Math: input is scalar per element, so the 1->4->8->4->1 ReLU MLP collapses
// to out = (x>0 ? s_pos[l] : s_neg[l]) * x (ReLU masks depend only on
// sign(x)). Fully-streaming cache policy in BOTH directions (__ldcs/__stcs)
// to minimize L2 tag/LRU churn; neither stream is re-read within a replay.
__global__ __launch_bounds__(TPB, 10) void fused_mlp_stream(
    const float4* __restrict__ X, float4* __restrict__ O,
    const float* __restrict__ w1,   // (NP,4,1)
    const float* __restrict__ w2,   // (NP,8,4)
    const float* __restrict__ w3,   // (NP,4,8)
    const float* __restrict__ w4) { // (NP,1,4)

    __shared__ float sw[72];        // [0:4) w1, [4:36) w2, [36:68) w3, [68:72) w4
    __shared__ float s_scale[2];

    const int l = blockIdx.y;
    const int t = threadIdx.x;

    // Parallel weight fetch (lanes 0..71, one load each).
    if (t < 72) {
        float v;
        if      (t < 4)  v = w1[l * 4  + t];
        else if (t < 36) v = w2[l * 32 + (t - 4)];
        else if (t < 68) v = w3[l * 32 + (t - 36)];
        else             v = w4[l * 4  + (t - 68)];
        sw[t] = v;
    }
    __syncthreads();

    // Two threads compute the two collapsed scalars (t=0: x>0, t=1: x<0).
    if (t < 2) {
        const bool pos = (t == 0);
        const float* W1 = sw;
        const float* W2 = sw + 4;
        const float* W3 = sw + 36;
        const float* W4 = sw + 68;
        float a[4];
        #pragma unroll
        for (int i = 0; i < 4; ++i) {
            float w = W1[i];
            a[i] = (pos ? (w > 0.0f) : (w < 0.0f)) ? w : 0.0f;
        }
        float b[8];
        #pragma unroll
        for (int j = 0; j < 8; ++j) {
            float s = 0.0f;
            #pragma unroll
            for (int i = 0; i < 4; ++i) s += W2[j * 4 + i] * a[i];
            b[j] = (pos ? (s > 0.0f) : (s < 0.0f)) ? s : 0.0f;
        }
        float c[4];
        #pragma unroll
        for (int i = 0; i < 4; ++i) {
            float s = 0.0f;
            #pragma unroll
            for (int j = 0; j < 8; ++j) s += W3[i * 8 + j] * b[j];
            c[i] = (pos ? (s > 0.0f) : (s < 0.0f)) ? s : 0.0f;
        }
        float out = 0.0f;
        #pragma unroll
        for (int i = 0; i < 4; ++i) out += W4[i] * c[i];
        s_scale[t] = out;
    }
    __syncthreads();

    const float sp = s_scale[0];
    const float sn = s_scale[1];

    // Base of this block's exact 4000-float4 region within its l.
    const float4* __restrict__ xi = X + (long)l * B4_ + blockIdx.x * CHUNK + t;
    float4*       __restrict__ oi = O + (long)l * B4_ + blockIdx.x * CHUNK + t;

    #pragma unroll
    for (int it = 0; it < ITER; ++it) {
        float4 x[VPT];
        #pragma unroll
        for (int k = 0; k < VPT; ++k)
            x[k] = __ldcs(&xi[k * TPB]);          // evict-first streaming read
        #pragma unroll
        for (int k = 0; k < VPT; ++k) {
            float4 v = x[k];
            float4 o;
            o.x = (v.x > 0.0f ? sp : sn) * v.x;
            o.y = (v.y > 0.0f ? sp : sn) * v.y;
            o.z = (v.z > 0.0f ? sp : sn) * v.z;
            o.w = (v.w > 0.0f ? sp : sn) * v.w;
            __stcs(&oi[k * TPB], o);               // evict-first streaming write
        }
        xi += STEP;
        oi += STEP;
    }
}

extern "C" void kernel_launch(void* const* d_in, const int* in_sizes, int n_in,
                              void* d_out, int out_size) {
    const float* X  = (const float*)d_in[0];
    const float* w1 = (const float*)d_in[1];
    const float* w2 = (const float*)d_in[2];
    const float* w3 = (const float*)d_in[3];
    const float* w4 = (const float*)d_in[4];
    float* out = (float*)d_out;

    dim3 grid(B4_ / CHUNK, NP_);   // (25, 44) = 1100 blocks, exact
    fused_mlp_stream<<<grid, TPB>>>((const float4*)X, (float4*)out,
                                    w1, w2, w3, w4);
}